// round 1
// baseline (speedup 1.0000x reference)
#include <cuda_runtime.h>
#include <cuda_bf16.h>

// Problem constants
#define BDIM 1024
#define DIN  64
#define DHID 128
#define BN_EPS 1e-5f

// Scratch (device globals; no allocations allowed)
__device__ float g_At[DHID * BDIM];          // A^T: [k][i] = b1[k] + sum_d x[i][d] W1[d][k]
__device__ float g_Ct[DHID * BDIM];          // C^T: [k][j] = sum_d x[j][d] W1[64+d][k]
__device__ float g_sorted[DHID * BDIM];      // per-channel sorted C values
__device__ float g_suf[DHID * (BDIM + 1)];   // suffix sums of sorted C  (index m: sum_{j>=m})
__device__ float g_suf2[DHID * (BDIM + 1)];  // suffix sums of sorted C^2
__device__ float g_S[DHID];                  // per-channel sum of relu(h)
__device__ float g_Q[DHID];                  // per-channel sum of relu(h)^2
__device__ float g_s[DHID];                  // folded scale  gamma*rsigma*W2
__device__ float g_t[1];                     // folded bias

// ---------------------------------------------------------------------------
// Kernel 1: A^T / C^T precompute.  grid=256 blocks (4 rows each), 128 threads.
// ---------------------------------------------------------------------------
__global__ __launch_bounds__(128) void prep_kernel(
    const float* __restrict__ x, const float* __restrict__ W1,
    const float* __restrict__ b1)
{
    __shared__ float xs[4][DIN];
    const int i0 = blockIdx.x * 4;
    const int tid = threadIdx.x;
    for (int e = tid; e < 4 * DIN; e += 128)
        xs[e >> 6][e & 63] = x[i0 * DIN + e];
    __syncthreads();

    const int k = tid;  // one thread per output channel
    float accA[4], accC[4];
#pragma unroll
    for (int r = 0; r < 4; r++) { accA[r] = b1[k]; accC[r] = 0.f; }
#pragma unroll 8
    for (int d = 0; d < DIN; d++) {
        const float w1 = W1[d * DHID + k];
        const float w2 = W1[(d + DIN) * DHID + k];
#pragma unroll
        for (int r = 0; r < 4; r++) {
            const float xv = xs[r][d];
            accA[r] = fmaf(xv, w1, accA[r]);
            accC[r] = fmaf(xv, w2, accC[r]);
        }
    }
#pragma unroll
    for (int r = 0; r < 4; r++) {
        g_At[k * BDIM + i0 + r] = accA[r];
        g_Ct[k * BDIM + i0 + r] = accC[r];
    }
}

// ---------------------------------------------------------------------------
// Kernel 2: per-channel bitonic sort of C + suffix sums (values and squares).
// grid=128 (one block per channel), 1024 threads.
// ---------------------------------------------------------------------------
__global__ __launch_bounds__(1024) void sort_scan_kernel()
{
    __shared__ float sc[BDIM];
    __shared__ float sbuf[BDIM];
    const int k = blockIdx.x;
    const int tid = threadIdx.x;

    sc[tid] = g_Ct[k * BDIM + tid];
    __syncthreads();

    // Bitonic sort ascending
    for (int size = 2; size <= BDIM; size <<= 1) {
        for (int stride = size >> 1; stride > 0; stride >>= 1) {
            const int p = tid ^ stride;
            if (p > tid) {
                const float a = sc[tid], b = sc[p];
                const bool up = ((tid & size) == 0);
                if ((a > b) == up) { sc[tid] = b; sc[p] = a; }
            }
            __syncthreads();
        }
    }
    g_sorted[k * BDIM + tid] = sc[tid];

    // Inclusive suffix scan of values
    sbuf[tid] = sc[tid];
    __syncthreads();
    for (int off = 1; off < BDIM; off <<= 1) {
        const float v = sbuf[tid] + ((tid + off) < BDIM ? sbuf[tid + off] : 0.f);
        __syncthreads();
        sbuf[tid] = v;
        __syncthreads();
    }
    g_suf[k * (BDIM + 1) + tid] = sbuf[tid];
    if (tid == 0) g_suf[k * (BDIM + 1) + BDIM] = 0.f;

    // Inclusive suffix scan of squares
    sbuf[tid] = sc[tid] * sc[tid];
    __syncthreads();
    for (int off = 1; off < BDIM; off <<= 1) {
        const float v = sbuf[tid] + ((tid + off) < BDIM ? sbuf[tid + off] : 0.f);
        __syncthreads();
        sbuf[tid] = v;
        __syncthreads();
    }
    g_suf2[k * (BDIM + 1) + tid] = sbuf[tid];
    if (tid == 0) g_suf2[k * (BDIM + 1) + BDIM] = 0.f;
}

// ---------------------------------------------------------------------------
// Kernel 3: per-channel stats via binary search.
//   sum_j relu(a_i + c_j)   = n*a + suf[m]
//   sum_j relu(a_i + c_j)^2 = n*a^2 + 2a*suf[m] + suf2[m]
// where m = first sorted index with c > -a, n = 1024 - m.
// grid=128, 256 threads.
// ---------------------------------------------------------------------------
__global__ __launch_bounds__(256) void stats_kernel()
{
    __shared__ float sc[BDIM];
    __shared__ float ssf[BDIM + 1];
    __shared__ float ssf2[BDIM + 1];
    __shared__ float redS[256];
    __shared__ float redQ[256];
    const int k = blockIdx.x;
    const int tid = threadIdx.x;

    for (int e = tid; e < BDIM; e += 256) sc[e] = g_sorted[k * BDIM + e];
    for (int e = tid; e < BDIM + 1; e += 256) {
        ssf[e]  = g_suf[k * (BDIM + 1) + e];
        ssf2[e] = g_suf2[k * (BDIM + 1) + e];
    }
    __syncthreads();

    float S = 0.f, Q = 0.f;
    for (int i = tid; i < BDIM; i += 256) {
        const float a = g_At[k * BDIM + i];
        const float th = -a;
        int lo = 0, hi = BDIM;
        while (lo < hi) {
            const int mid = (lo + hi) >> 1;
            if (sc[mid] > th) hi = mid; else lo = mid + 1;
        }
        const float n  = (float)(BDIM - lo);
        const float s1 = ssf[lo];
        const float s2 = ssf2[lo];
        S += fmaf(n, a, s1);
        Q += fmaf(n * a, a, fmaf(2.f * a, s1, s2));
    }
    redS[tid] = S; redQ[tid] = Q;
    __syncthreads();
    for (int s = 128; s > 0; s >>= 1) {
        if (tid < s) { redS[tid] += redS[tid + s]; redQ[tid] += redQ[tid + s]; }
        __syncthreads();
    }
    if (tid == 0) { g_S[k] = redS[0]; g_Q[k] = redQ[0]; }
}

// ---------------------------------------------------------------------------
// Kernel 4: fold BN + final linear into (s[k], t).  1 block, 128 threads.
// ---------------------------------------------------------------------------
__global__ __launch_bounds__(128) void finalize_kernel(
    const float* __restrict__ gamma, const float* __restrict__ beta,
    const float* __restrict__ W2, const float* __restrict__ b2)
{
    __shared__ float red[128];
    const int k = threadIdx.x;
    const float N = (float)BDIM * (float)BDIM;
    const float mean = g_S[k] / N;
    const float var  = g_Q[k] / N - mean * mean;
    const float rs   = rsqrtf(var + BN_EPS);
    const float w    = W2[k];
    g_s[k] = gamma[k] * rs * w;
    red[k] = (beta[k] - mean * rs * gamma[k]) * w;
    __syncthreads();
    for (int s = 64; s > 0; s >>= 1) {
        if (k < s) red[k] += red[k + s];
        __syncthreads();
    }
    if (k == 0) g_t[0] = red[0] + b2[0];
}

// ---------------------------------------------------------------------------
// Kernel 5 (dominant): out[i][j] = t + sum_k s[k] * relu(At[k][i] + Ct[k][j])
// 64x64 tile per block, 256 threads, 4x4 register tile per thread,
// k-dimension processed in two 64-chunks through shared memory (k-major tiles
// so compute reads are conflict-free float4 LDS).
// ---------------------------------------------------------------------------
__global__ __launch_bounds__(256) void pass2_kernel(float* __restrict__ out)
{
    __shared__ float As[64][64];   // [kk][i]
    __shared__ float Cs[64][64];   // [kk][j]
    __shared__ float sS[DHID];

    const int i0 = blockIdx.y * 64;
    const int j0 = blockIdx.x * 64;
    const int tid = threadIdx.x;
    if (tid < DHID) sS[tid] = g_s[tid];

    const int ty = tid >> 4;   // 0..15 -> i sub-tile
    const int tx = tid & 15;   // 0..15 -> j sub-tile

    float acc[4][4];
#pragma unroll
    for (int q = 0; q < 4; q++)
#pragma unroll
        for (int r = 0; r < 4; r++) acc[q][r] = 0.f;

    for (int kc = 0; kc < 2; kc++) {
        __syncthreads();
        for (int e = tid; e < 64 * 16; e += 256) {
            const int kk = e >> 4, v = e & 15;
            const int kg = kc * 64 + kk;
            *(float4*)&As[kk][v * 4] = *(const float4*)&g_At[kg * BDIM + i0 + v * 4];
            *(float4*)&Cs[kk][v * 4] = *(const float4*)&g_Ct[kg * BDIM + j0 + v * 4];
        }
        __syncthreads();

#pragma unroll 8
        for (int kk = 0; kk < 64; kk++) {
            const float4 a4 = *(const float4*)&As[kk][ty * 4];
            const float4 c4 = *(const float4*)&Cs[kk][tx * 4];
            const float sk = sS[kc * 64 + kk];
            const float av[4] = {a4.x, a4.y, a4.z, a4.w};
            const float cv[4] = {c4.x, c4.y, c4.z, c4.w};
#pragma unroll
            for (int q = 0; q < 4; q++)
#pragma unroll
                for (int r = 0; r < 4; r++)
                    acc[q][r] = fmaf(fmaxf(av[q] + cv[r], 0.f), sk, acc[q][r]);
        }
    }

    const float t = g_t[0];
#pragma unroll
    for (int q = 0; q < 4; q++) {
        float4 o;
        o.x = acc[q][0] + t;
        o.y = acc[q][1] + t;
        o.z = acc[q][2] + t;
        o.w = acc[q][3] + t;
        *(float4*)&out[(size_t)(i0 + ty * 4 + q) * BDIM + j0 + tx * 4] = o;
    }
}

// ---------------------------------------------------------------------------
extern "C" void kernel_launch(void* const* d_in, const int* in_sizes, int n_in,
                              void* d_out, int out_size)
{
    const float* x     = (const float*)d_in[0];
    const float* W1    = (const float*)d_in[1];
    const float* b1    = (const float*)d_in[2];
    const float* gamma = (const float*)d_in[3];
    const float* beta  = (const float*)d_in[4];
    const float* W2    = (const float*)d_in[5];
    const float* b2    = (const float*)d_in[6];
    float* out = (float*)d_out;

    prep_kernel<<<BDIM / 4, 128>>>(x, W1, b1);
    sort_scan_kernel<<<DHID, 1024>>>();
    stats_kernel<<<DHID, 256>>>();
    finalize_kernel<<<1, 128>>>(gamma, beta, W2, b2);
    pass2_kernel<<<dim3(16, 16), 256>>>(out);
}

// round 2
// speedup vs baseline: 1.2655x; 1.2655x over previous
#include <cuda_runtime.h>
#include <cuda_bf16.h>
#include <cstdint>

// Problem constants
#define BDIM 1024
#define DIN  64
#define DHID 128
#define BN_EPS 1e-5f

// Scratch (device globals; no allocations allowed)
__device__ float g_At[DHID * BDIM];   // A^T: [k][i] = b1[k] + sum_d x[i][d] W1[d][k]
__device__ float g_Ct[DHID * BDIM];   // C^T: [k][j] = sum_d x[j][d] W1[64+d][k]
__device__ float g_s[DHID];           // folded scale  gamma*rsigma*W2
__device__ float g_tpart[DHID];       // per-channel bias contribution
__device__ float g_t[1];              // folded bias
__device__ float g_P[BDIM];           // 0.5 * sum_k s_k * At[k][i]
__device__ float g_R[BDIM];           // 0.5 * sum_k s_k * Ct[k][j]

// ---------------------------------------------------------------------------
// Kernel 1: A^T / C^T precompute.  grid=256 blocks (4 rows each), 128 threads.
// ---------------------------------------------------------------------------
__global__ __launch_bounds__(128) void prep_kernel(
    const float* __restrict__ x, const float* __restrict__ W1,
    const float* __restrict__ b1)
{
    __shared__ float xs[4][DIN];
    const int i0 = blockIdx.x * 4;
    const int tid = threadIdx.x;
    for (int e = tid; e < 4 * DIN; e += 128)
        xs[e >> 6][e & 63] = x[i0 * DIN + e];
    __syncthreads();

    const int k = tid;
    float accA[4], accC[4];
#pragma unroll
    for (int r = 0; r < 4; r++) { accA[r] = b1[k]; accC[r] = 0.f; }
#pragma unroll 8
    for (int d = 0; d < DIN; d++) {
        const float w1 = W1[d * DHID + k];
        const float w2 = W1[(d + DIN) * DHID + k];
#pragma unroll
        for (int r = 0; r < 4; r++) {
            const float xv = xs[r][d];
            accA[r] = fmaf(xv, w1, accA[r]);
            accC[r] = fmaf(xv, w2, accC[r]);
        }
    }
#pragma unroll
    for (int r = 0; r < 4; r++) {
        g_At[k * BDIM + i0 + r] = accA[r];
        g_Ct[k * BDIM + i0 + r] = accC[r];
    }
}

// ---------------------------------------------------------------------------
// Kernel 2 (fused): per-channel register bitonic sort (shfl for stride<32),
// shfl-based suffix scans of C and C^2, binary-search stats, BN fold.
// grid=128 (one block per channel), 1024 threads.
// ---------------------------------------------------------------------------
__global__ __launch_bounds__(1024) void sortstats_kernel(
    const float* __restrict__ gamma, const float* __restrict__ beta,
    const float* __restrict__ W2)
{
    __shared__ float sc[BDIM];
    __shared__ float ssf[BDIM + 2];
    __shared__ float ssf2[BDIM + 2];
    __shared__ float wr1[32];
    __shared__ float wr2[32];

    const int k = blockIdx.x;
    const int tid = threadIdx.x;
    const int lane = tid & 31;
    const int warp = tid >> 5;

    float v = g_Ct[k * BDIM + tid];

    // Bitonic sort ascending across tid (value lives in register).
    for (int size = 2; size <= BDIM; size <<= 1) {
        for (int stride = size >> 1; stride > 0; stride >>= 1) {
            float other;
            if (stride >= 32) {
                sc[tid] = v;
                __syncthreads();
                other = sc[tid ^ stride];
                __syncthreads();
            } else {
                other = __shfl_xor_sync(0xffffffffu, v, stride);
            }
            const bool up = ((tid & size) == 0);
            const bool lower = ((tid & stride) == 0);
            const float mn = fminf(v, other);
            const float mx = fmaxf(v, other);
            v = (up == lower) ? mn : mx;
        }
    }
    sc[tid] = v;   // sorted ascending

    // Inclusive suffix sums of v and v^2 (warp shfl + warp-total combine).
    float w1 = v, w2 = v * v;
#pragma unroll
    for (int o = 1; o < 32; o <<= 1) {
        const float t1 = __shfl_down_sync(0xffffffffu, w1, o);
        const float t2 = __shfl_down_sync(0xffffffffu, w2, o);
        if (lane + o < 32) { w1 += t1; w2 += t2; }
    }
    if (lane == 0) { wr1[warp] = w1; wr2[warp] = w2; }
    __syncthreads();
    if (warp == 0) {
        const float o1 = wr1[lane];
        const float o2 = wr2[lane];
        float i1 = o1, i2 = o2;
#pragma unroll
        for (int o = 1; o < 32; o <<= 1) {
            const float t1 = __shfl_down_sync(0xffffffffu, i1, o);
            const float t2 = __shfl_down_sync(0xffffffffu, i2, o);
            if (lane + o < 32) { i1 += t1; i2 += t2; }
        }
        wr1[lane] = i1 - o1;   // exclusive suffix over later warps
        wr2[lane] = i2 - o2;
    }
    __syncthreads();
    ssf[tid]  = w1 + wr1[warp];
    ssf2[tid] = w2 + wr2[warp];
    if (tid == 0) { ssf[BDIM] = 0.f; ssf2[BDIM] = 0.f; }
    __syncthreads();

    // Binary-search based stats: one (i) per thread.
    //   sum_j relu(a+c_j)   = n*a + suf[m]
    //   sum_j relu(a+c_j)^2 = n*a^2 + 2a*suf[m] + suf2[m]
    const float a = g_At[k * BDIM + tid];
    const float th = -a;
    int lo = 0, hi = BDIM;
#pragma unroll
    for (int it = 0; it < 10; it++) {
        const int mid = (lo + hi) >> 1;
        if (sc[mid] > th) hi = mid; else lo = mid + 1;
        // after 10 halvings lo==hi
        hi = (lo < hi) ? hi : lo;
        lo = (lo < hi) ? lo : hi;
    }
    const float n  = (float)(BDIM - lo);
    const float s1 = ssf[lo];
    const float s2 = ssf2[lo];
    float S = fmaf(n, a, s1);
    float Q = fmaf(n * a, a, fmaf(2.f * a, s1, s2));

    // block reduce S, Q
#pragma unroll
    for (int o = 16; o > 0; o >>= 1) {
        S += __shfl_xor_sync(0xffffffffu, S, o);
        Q += __shfl_xor_sync(0xffffffffu, Q, o);
    }
    __syncthreads();   // wr1/wr2 reuse
    if (lane == 0) { wr1[warp] = S; wr2[warp] = Q; }
    __syncthreads();
    if (tid == 0) {
        float St = 0.f, Qt = 0.f;
#pragma unroll
        for (int w = 0; w < 32; w++) { St += wr1[w]; Qt += wr2[w]; }
        const float N = (float)BDIM * (float)BDIM;
        const float mean = St / N;
        const float var  = Qt / N - mean * mean;
        const float rs   = rsqrtf(var + BN_EPS);
        const float wk   = W2[k];
        g_s[k] = gamma[k] * rs * wk;
        g_tpart[k] = (beta[k] - mean * rs * gamma[k]) * wk;
    }
}

// ---------------------------------------------------------------------------
// Kernel 3: block 0 reduces t; blocks 1..8 compute P chunks; 9..16 R chunks.
// P_i = 0.5 * sum_k s_k At[k][i]  (half folded in; t kept separate)
// ---------------------------------------------------------------------------
__global__ __launch_bounds__(128) void finalize_pr_kernel(const float* __restrict__ b2)
{
    const int b = blockIdx.x;
    const int tid = threadIdx.x;
    if (b == 0) {
        __shared__ float red[128];
        red[tid] = g_tpart[tid];
        __syncthreads();
        for (int s = 64; s > 0; s >>= 1) {
            if (tid < s) red[tid] += red[tid + s];
            __syncthreads();
        }
        if (tid == 0) g_t[0] = red[0] + b2[0];
    } else {
        __shared__ float ss[DHID];
        ss[tid] = g_s[tid];
        __syncthreads();
        const bool isP = (b <= 8);
        const int idx = ((b - 1) & 7) * 128 + tid;
        const float* src = isP ? g_At : g_Ct;
        float acc = 0.f;
#pragma unroll 16
        for (int k = 0; k < DHID; k++)
            acc = fmaf(ss[k], src[k * BDIM + idx], acc);
        if (isP) g_P[idx] = 0.5f * acc;
        else     g_R[idx] = 0.5f * acc;
    }
}

// ---------------------------------------------------------------------------
// Kernel 4 (dominant): out[i][j] = t + P_i + R_j + sum_k (s_k/2)|At[k][i]+Ct[k][j]|
// 64x64 tile per block, 256 threads, 4x4 per thread, packed f32x2 math.
// ---------------------------------------------------------------------------
__global__ __launch_bounds__(256) void pass2_kernel(float* __restrict__ out)
{
    __shared__ float As[64][64];          // [kk][i]
    __shared__ float Cs[64][64];          // [kk][j]
    __shared__ unsigned long long s2h[DHID];  // (s/2, s/2) packed
    __shared__ float Ps[64];
    __shared__ float Rs[64];

    const int i0 = blockIdx.y * 64;
    const int j0 = blockIdx.x * 64;
    const int tid = threadIdx.x;

    if (tid < DHID) {
        const float sh = 0.5f * g_s[tid];
        unsigned long long p;
        asm("mov.b64 %0, {%1, %1};" : "=l"(p) : "f"(sh));
        s2h[tid] = p;
    }
    if (tid < 64) Ps[tid] = g_P[i0 + tid];
    else if (tid < 128) Rs[tid - 64] = g_R[j0 + tid - 64];

    const int ty = tid >> 4;   // 0..15 -> i sub-tile
    const int tx = tid & 15;   // 0..15 -> j sub-tile

    unsigned long long acc2[4][2];
#pragma unroll
    for (int q = 0; q < 4; q++) { acc2[q][0] = 0ull; acc2[q][1] = 0ull; }

    const unsigned long long MASK = 0x7FFFFFFF7FFFFFFFull;

    for (int kc = 0; kc < 2; kc++) {
        __syncthreads();
        for (int e = tid; e < 64 * 16; e += 256) {
            const int kk = e >> 4, vv = e & 15;
            const int kg = kc * 64 + kk;
            *(float4*)&As[kk][vv * 4] = *(const float4*)&g_At[kg * BDIM + i0 + vv * 4];
            *(float4*)&Cs[kk][vv * 4] = *(const float4*)&g_Ct[kg * BDIM + j0 + vv * 4];
        }
        __syncthreads();

#pragma unroll 8
        for (int kk = 0; kk < 64; kk++) {
            const float4 a4 = *(const float4*)&As[kk][ty * 4];
            const ulonglong2 c2 = *(const ulonglong2*)&Cs[kk][tx * 4];
            const unsigned long long sk = s2h[kc * 64 + kk];
            unsigned long long a2[4];
            asm("mov.b64 %0, {%1, %1};" : "=l"(a2[0]) : "f"(a4.x));
            asm("mov.b64 %0, {%1, %1};" : "=l"(a2[1]) : "f"(a4.y));
            asm("mov.b64 %0, {%1, %1};" : "=l"(a2[2]) : "f"(a4.z));
            asm("mov.b64 %0, {%1, %1};" : "=l"(a2[3]) : "f"(a4.w));
#pragma unroll
            for (int q = 0; q < 4; q++) {
#pragma unroll
                for (int rr = 0; rr < 2; rr++) {
                    unsigned long long vsum;
                    const unsigned long long cc = (rr == 0) ? c2.x : c2.y;
                    asm("add.rn.f32x2 %0, %1, %2;" : "=l"(vsum) : "l"(a2[q]), "l"(cc));
                    vsum &= MASK;   // |.| on both packed lanes
                    asm("fma.rn.f32x2 %0, %1, %2, %3;"
                        : "=l"(acc2[q][rr]) : "l"(vsum), "l"(sk), "l"(acc2[q][rr]));
                }
            }
        }
    }

    const float t = g_t[0];
#pragma unroll
    for (int q = 0; q < 4; q++) {
        float r0, r1, r2, r3;
        asm("mov.b64 {%0, %1}, %2;" : "=f"(r0), "=f"(r1) : "l"(acc2[q][0]));
        asm("mov.b64 {%0, %1}, %2;" : "=f"(r2), "=f"(r3) : "l"(acc2[q][1]));
        const float base = t + Ps[ty * 4 + q];
        float4 o;
        o.x = r0 + base + Rs[tx * 4 + 0];
        o.y = r1 + base + Rs[tx * 4 + 1];
        o.z = r2 + base + Rs[tx * 4 + 2];
        o.w = r3 + base + Rs[tx * 4 + 3];
        *(float4*)&out[(size_t)(i0 + ty * 4 + q) * BDIM + j0 + tx * 4] = o;
    }
}

// ---------------------------------------------------------------------------
extern "C" void kernel_launch(void* const* d_in, const int* in_sizes, int n_in,
                              void* d_out, int out_size)
{
    const float* x     = (const float*)d_in[0];
    const float* W1    = (const float*)d_in[1];
    const float* b1    = (const float*)d_in[2];
    const float* gamma = (const float*)d_in[3];
    const float* beta  = (const float*)d_in[4];
    const float* W2    = (const float*)d_in[5];
    const float* b2    = (const float*)d_in[6];
    float* out = (float*)d_out;

    prep_kernel<<<BDIM / 4, 128>>>(x, W1, b1);
    sortstats_kernel<<<DHID, 1024>>>(gamma, beta, W2);
    finalize_pr_kernel<<<17, 128>>>(b2);
    pass2_kernel<<<dim3(16, 16), 256>>>(out);
}